// round 10
// baseline (speedup 1.0000x reference)
#include <cuda_runtime.h>
#include <math.h>

#define NCOLS  16384
#define NT     256
#define V4     (NCOLS / 4 / NT)     // 16 float4 per thread
#define KSEL   256
#define CAP    2048
#define NW     (NT / 32)
#define RST    8

__global__ __launch_bounds__(NT, 8)
void entmax_topk_kernel(const float* __restrict__ logits,
                        float* __restrict__ out_w,
                        float* __restrict__ out_cnt)
{
    __shared__ float cand[CAP];
    __shared__ float s_f[NW];
    __shared__ int   s_i[NW];
    __shared__ float s_tau, s_th, s_inv;
    __shared__ int   s_useGe;

    const int tid  = threadIdx.x;
    const int lane = tid & 31;
    const int wid  = tid >> 5;
    const int row  = blockIdx.x;

    const float4* src = reinterpret_cast<const float4*>(logits) + (size_t)row * (NCOLS / 4);
    float4*       dst = reinterpret_cast<float4*>(out_w)        + (size_t)row * (NCOLS / 4);

    // ---------- Pass A: row max (default policy -> row stays hot in L2) ----------
    float lmax = -INFINITY;
    #pragma unroll 4
    for (int j = 0; j < V4; ++j) {
        float4 t = src[tid + j * NT];
        lmax = fmaxf(lmax, fmaxf(fmaxf(t.x, t.y), fmaxf(t.z, t.w)));
    }
    #pragma unroll
    for (int o = 16; o; o >>= 1) lmax = fmaxf(lmax, __shfl_xor_sync(0xffffffffu, lmax, o));
    if (lane == 0) s_f[wid] = lmax;
    __syncthreads();                                 // barrier 1
    float zmax;
    {
        float m = (lane < NW) ? s_f[lane] : -INFINITY;
        #pragma unroll
        for (int o = 4; o; o >>= 1) m = fmaxf(m, __shfl_xor_sync(0xffffffffu, m, o));
        zmax = 0.5f * __shfl_sync(0xffffffffu, m, 0);
    }
    const float cutoff = zmax - 1.0f;                // rigorous lower bound on tau

    // ---------- Pass B: L2 re-read, stash candidates z > cutoff (true cutoff) ----------
    float stash[RST];
    int lc = 0;
    #pragma unroll 4
    for (int j = 0; j < V4; ++j) {
        float4 t = src[tid + j * NT];                // L2 hit
        float z;
        z = 0.5f * t.x; if (z > cutoff) { if (lc < RST) stash[lc] = z; ++lc; }
        z = 0.5f * t.y; if (z > cutoff) { if (lc < RST) stash[lc] = z; ++lc; }
        z = 0.5f * t.z; if (z > cutoff) { if (lc < RST) stash[lc] = z; ++lc; }
        z = 0.5f * t.w; if (z > cutoff) { if (lc < RST) stash[lc] = z; ++lc; }
    }
    // deterministic exclusive scan of per-thread counts
    int inc = lc;
    #pragma unroll
    for (int o = 1; o < 32; o <<= 1) {
        int t = __shfl_up_sync(0xffffffffu, inc, o);
        if (lane >= o) inc += t;
    }
    if (lane == 31) s_i[wid] = inc;
    __syncthreads();                                 // barrier 2
    int wbase, cn;
    {
        int a = (lane < NW) ? s_i[lane] : 0;
        int sc = a;
        #pragma unroll
        for (int o = 1; o < NW; o <<= 1) {
            int u = __shfl_up_sync(0xffffffffu, sc, o);
            if (lane >= o) sc += u;
        }
        cn    = __shfl_sync(0xffffffffu, sc, NW - 1);
        wbase = __shfl_sync(0xffffffffu, sc - a, wid);
    }
    const bool useSmem = (cn <= CAP);
    if (useSmem && lc > 0) {
        int o = wbase + (inc - lc);
        if (lc <= RST) {
            for (int k = 0; k < lc; ++k) cand[o + k] = stash[k];
        } else {   // stash overflow (P ~ 1e-8 per thread): deterministic L2 re-read
            int w = 0;
            #pragma unroll 4
            for (int j = 0; j < V4; ++j) {
                float4 t = src[tid + j * NT];
                float z;
                z = 0.5f * t.x; if (z > cutoff) cand[o + w++] = z;
                z = 0.5f * t.y; if (z > cutoff) cand[o + w++] = z;
                z = 0.5f * t.z; if (z > cutoff) cand[o + w++] = z;
                z = 0.5f * t.w; if (z > cutoff) cand[o + w++] = z;
            }
        }
    }
    __syncthreads();                                 // barrier 3

    // ---------- warp 0: solve tau/th/inv AND num_selected ----------
    if (wid == 0) {
        float tau = cutoff, th, inv;
        int useGe = 0, sel = 0;

        if (useSmem && cn <= 256) {
            float rv[8];
            #pragma unroll
            for (int r = 0; r < 8; ++r) {
                int idx = r * 32 + lane;
                rv[r] = (idx < cn) ? cand[idx] : -1e30f;
            }
            float gfin = 0.f;
            for (int it = 0; it < 24; ++it) {
                float g = 0.f, gp = 0.f;
                #pragma unroll
                for (int r = 0; r < 8; ++r) {
                    float d = rv[r] - tau;
                    if (d > 0.f) { g = fmaf(d, d, g); gp += d; }
                }
                #pragma unroll
                for (int o = 16; o; o >>= 1) {
                    g  += __shfl_xor_sync(0xffffffffu, g,  o);
                    gp += __shfl_xor_sync(0xffffffffu, gp, o);
                }
                gfin = g;
                g -= 1.0f;
                if (gp <= 0.f) break;
                float step = g / (2.0f * gp);
                tau += step;
                if (step < 1e-7f) break;
            }
            int S = 0;
            #pragma unroll
            for (int r = 0; r < 8; ++r) S += (rv[r] > tau) ? 1 : 0;
            #pragma unroll
            for (int o = 16; o; o >>= 1) S += __shfl_xor_sync(0xffffffffu, S, o);

            th = tau;
            float ssum = gfin;
            if (S > KSEL) {                          // rare: bisect K-th largest z
                useGe = 1;
                float lo = tau, hi = zmax;
                for (int it = 0; it < 48; ++it) {
                    float mid = 0.5f * (lo + hi);
                    int c = 0;
                    #pragma unroll
                    for (int r = 0; r < 8; ++r) c += (rv[r] >= mid) ? 1 : 0;
                    #pragma unroll
                    for (int o = 16; o; o >>= 1) c += __shfl_xor_sync(0xffffffffu, c, o);
                    if (c >= KSEL) lo = mid; else hi = mid;
                }
                th = lo;
                ssum = 0.f;
                #pragma unroll
                for (int r = 0; r < 8; ++r) {
                    float z = rv[r], d = z - tau;
                    if (z >= th && d > 0.f) ssum = fmaf(d, d, ssum);
                }
                #pragma unroll
                for (int o = 16; o; o >>= 1) ssum += __shfl_xor_sync(0xffffffffu, ssum, o);
            }
            inv = 1.0f / (ssum + 1e-8f);
            #pragma unroll
            for (int r = 0; r < 8; ++r) {            // exact num_selected
                float z = rv[r], d = z - tau;
                bool keep = useGe ? (z >= th && d > 0.f) : (d > 0.f);
                float w = keep ? d * d * inv : 0.f;
                sel += (w > 1e-6f);
            }
        } else {
            const float* cb = useSmem ? cand : (logits + (size_t)row * NCOLS);
            const float  sc = useSmem ? 1.0f : 0.5f;
            const int    n  = useSmem ? cn : NCOLS;

            float gfin = 0.f;
            for (int it = 0; it < 24; ++it) {
                float g = 0.f, gp = 0.f;
                for (int i = lane; i < n; i += 32) {
                    float d = sc * cb[i] - tau;
                    if (d > 0.f) { g = fmaf(d, d, g); gp += d; }
                }
                #pragma unroll
                for (int o = 16; o; o >>= 1) {
                    g  += __shfl_xor_sync(0xffffffffu, g,  o);
                    gp += __shfl_xor_sync(0xffffffffu, gp, o);
                }
                gfin = g;
                g -= 1.0f;
                if (gp <= 0.f) break;
                float step = g / (2.0f * gp);
                tau += step;
                if (step < 1e-7f) break;
            }
            int S = 0;
            for (int i = lane; i < n; i += 32) S += (sc * cb[i] > tau) ? 1 : 0;
            #pragma unroll
            for (int o = 16; o; o >>= 1) S += __shfl_xor_sync(0xffffffffu, S, o);

            th = tau;
            float ssum = gfin;
            if (S > KSEL) {
                useGe = 1;
                float lo = tau, hi = zmax;
                for (int it = 0; it < 48; ++it) {
                    float mid = 0.5f * (lo + hi);
                    int c = 0;
                    for (int i = lane; i < n; i += 32) c += (sc * cb[i] >= mid) ? 1 : 0;
                    #pragma unroll
                    for (int o = 16; o; o >>= 1) c += __shfl_xor_sync(0xffffffffu, c, o);
                    if (c >= KSEL) lo = mid; else hi = mid;
                }
                th = lo;
                ssum = 0.f;
                for (int i = lane; i < n; i += 32) {
                    float z = sc * cb[i], d = z - tau;
                    if (z >= th && d > 0.f) ssum = fmaf(d, d, ssum);
                }
                #pragma unroll
                for (int o = 16; o; o >>= 1) ssum += __shfl_xor_sync(0xffffffffu, ssum, o);
            }
            inv = 1.0f / (ssum + 1e-8f);
            for (int i = lane; i < n; i += 32) {
                float z = sc * cb[i], d = z - tau;
                bool keep = useGe ? (z >= th && d > 0.f) : (d > 0.f);
                float w = keep ? d * d * inv : 0.f;
                sel += (w > 1e-6f);
            }
        }
        #pragma unroll
        for (int o = 16; o; o >>= 1) sel += __shfl_xor_sync(0xffffffffu, sel, o);
        if (lane == 0) {
            s_tau = tau; s_th = th; s_useGe = useGe; s_inv = inv;
            out_cnt[row] = (float)sel;
        }
    }
    __syncthreads();                                 // barrier 4 (last)

    const float tau = s_tau, th = s_th, inv = s_inv;
    const bool  useGe = (s_useGe != 0);

    // ---------- Output: barrier-free stream (L2 re-read -> weights -> __stcs) ----------
    #pragma unroll 4
    for (int j = 0; j < V4; ++j) {
        float4 t = src[tid + j * NT];                // L2 hit
        float4 w;
        {
            float z = 0.5f * t.x, d = z - tau;
            bool keep = useGe ? (z >= th && d > 0.f) : (d > 0.f);
            w.x = keep ? d * d * inv : 0.f;
        }
        {
            float z = 0.5f * t.y, d = z - tau;
            bool keep = useGe ? (z >= th && d > 0.f) : (d > 0.f);
            w.y = keep ? d * d * inv : 0.f;
        }
        {
            float z = 0.5f * t.z, d = z - tau;
            bool keep = useGe ? (z >= th && d > 0.f) : (d > 0.f);
            w.z = keep ? d * d * inv : 0.f;
        }
        {
            float z = 0.5f * t.w, d = z - tau;
            bool keep = useGe ? (z >= th && d > 0.f) : (d > 0.f);
            w.w = keep ? d * d * inv : 0.f;
        }
        __stcs(&dst[tid + j * NT], w);
    }
}

extern "C" void kernel_launch(void* const* d_in, const int* in_sizes, int n_in,
                              void* d_out, int out_size)
{
    const float* logits = (const float*)d_in[0];
    float* out = (float*)d_out;
    const int B = in_sizes[0] / NCOLS;
    entmax_topk_kernel<<<B, NT>>>(logits, out, out + (size_t)B * NCOLS);
}

// round 11
// speedup vs baseline: 1.0742x; 1.0742x over previous
#include <cuda_runtime.h>
#include <math.h>

#define NCOLS  16384
#define NT     256
#define V4     (NCOLS / 4 / NT)     // 16 float4 per thread
#define KSEL   256
#define CAP    2048
#define NW     (NT / 32)
#define RST    12
#define FTZ    0.70f                // fixed pre-threshold (z units)

__global__ __launch_bounds__(NT, 6)
void entmax_topk_kernel(const float* __restrict__ logits,
                        float* __restrict__ out_w,
                        float* __restrict__ out_cnt)
{
    __shared__ float cand[CAP];
    __shared__ float s_f[NW];
    __shared__ int   s_i[NW];
    __shared__ float s_tau, s_th, s_inv;
    __shared__ int   s_useGe;

    const int tid  = threadIdx.x;
    const int lane = tid & 31;
    const int wid  = tid >> 5;
    const int row  = blockIdx.x;

    const float4* src = reinterpret_cast<const float4*>(logits) + (size_t)row * (NCOLS / 4);
    float4*       dst = reinterpret_cast<float4*>(out_w)        + (size_t)row * (NCOLS / 4);

    // ---------- Pass A: ONE DRAM sweep = max + fixed-threshold stash ----------
    float stash[RST];
    int   lc = 0;
    float lmax = -INFINITY;
    #pragma unroll 4
    for (int j = 0; j < V4; ++j) {
        float4 t = src[tid + j * NT];               // default policy -> hot in L2
        float zx = 0.5f * t.x, zy = 0.5f * t.y, zz = 0.5f * t.z, zw = 0.5f * t.w;
        lmax = fmaxf(lmax, fmaxf(fmaxf(zx, zy), fmaxf(zz, zw)));
        if (zx > FTZ) { if (lc < RST) stash[lc] = zx; ++lc; }
        if (zy > FTZ) { if (lc < RST) stash[lc] = zy; ++lc; }
        if (zz > FTZ) { if (lc < RST) stash[lc] = zz; ++lc; }
        if (zw > FTZ) { if (lc < RST) stash[lc] = zw; ++lc; }
    }
    #pragma unroll
    for (int o = 16; o; o >>= 1) lmax = fmaxf(lmax, __shfl_xor_sync(0xffffffffu, lmax, o));
    if (lane == 0) s_f[wid] = lmax;
    __syncthreads();                                 // barrier 1
    float zmax;
    {
        float m = (lane < NW) ? s_f[lane] : -INFINITY;
        #pragma unroll
        for (int o = 4; o; o >>= 1) m = fmaxf(m, __shfl_xor_sync(0xffffffffu, m, o));
        zmax = __shfl_sync(0xffffffffu, m, 0);
    }
    const float cutoff = zmax - 1.0f;                // rigorous lower bound on tau
    // stash validity: candidates {z > cutoff} ⊆ stash requires cutoff >= FTZ
    const bool rowFB = (cutoff < FTZ);               // uniform across block (rare)
    const bool thFB  = (lc > RST);                   // this thread's stash overflowed (rare)
    const bool useStash = !rowFB && !thFB;

    // ---------- count true candidates ----------
    int lcf = 0;
    if (useStash) {
        #pragma unroll
        for (int k = 0; k < RST; ++k) lcf += (k < lc && stash[k] > cutoff);
    } else {                                          // deterministic L1/L2 re-read
        #pragma unroll 4
        for (int j = 0; j < V4; ++j) {
            float4 t = src[tid + j * NT];
            lcf += (0.5f * t.x > cutoff) + (0.5f * t.y > cutoff)
                 + (0.5f * t.z > cutoff) + (0.5f * t.w > cutoff);
        }
    }
    // deterministic exclusive scan of per-thread counts
    int inc = lcf;
    #pragma unroll
    for (int o = 1; o < 32; o <<= 1) {
        int t = __shfl_up_sync(0xffffffffu, inc, o);
        if (lane >= o) inc += t;
    }
    if (lane == 31) s_i[wid] = inc;
    __syncthreads();                                 // barrier 2
    int wbase, cn;
    {
        int a = (lane < NW) ? s_i[lane] : 0;
        int sc = a;
        #pragma unroll
        for (int o = 1; o < NW; o <<= 1) {
            int u = __shfl_up_sync(0xffffffffu, sc, o);
            if (lane >= o) sc += u;
        }
        cn    = __shfl_sync(0xffffffffu, sc, NW - 1);
        wbase = __shfl_sync(0xffffffffu, sc - a, wid);
    }
    const bool useSmem = (cn <= CAP);
    if (useSmem && lcf > 0) {
        int o = wbase + (inc - lcf);
        if (useStash) {
            #pragma unroll
            for (int k = 0; k < RST; ++k)
                if (k < lc && stash[k] > cutoff) cand[o++] = stash[k];
        } else {
            #pragma unroll 4
            for (int j = 0; j < V4; ++j) {
                float4 t = src[tid + j * NT];        // L1/L2 hit
                float z;
                z = 0.5f * t.x; if (z > cutoff) cand[o++] = z;
                z = 0.5f * t.y; if (z > cutoff) cand[o++] = z;
                z = 0.5f * t.z; if (z > cutoff) cand[o++] = z;
                z = 0.5f * t.w; if (z > cutoff) cand[o++] = z;
            }
        }
    }
    __syncthreads();                                 // barrier 3

    // ---------- warp 0: solve tau/th/inv AND num_selected ----------
    if (wid == 0) {
        float tau = cutoff, th, inv;
        int useGe = 0, sel = 0;

        if (useSmem && cn <= 256) {
            float rv[8];
            #pragma unroll
            for (int r = 0; r < 8; ++r) {
                int idx = r * 32 + lane;
                rv[r] = (idx < cn) ? cand[idx] : -1e30f;
            }
            float gfin = 0.f;
            for (int it = 0; it < 24; ++it) {
                float g = 0.f, gp = 0.f;
                #pragma unroll
                for (int r = 0; r < 8; ++r) {
                    float d = rv[r] - tau;
                    if (d > 0.f) { g = fmaf(d, d, g); gp += d; }
                }
                #pragma unroll
                for (int o = 16; o; o >>= 1) {
                    g  += __shfl_xor_sync(0xffffffffu, g,  o);
                    gp += __shfl_xor_sync(0xffffffffu, gp, o);
                }
                gfin = g;
                g -= 1.0f;
                if (gp <= 0.f) break;
                float step = g / (2.0f * gp);
                tau += step;
                if (step < 1e-7f) break;
            }
            int S = 0;
            #pragma unroll
            for (int r = 0; r < 8; ++r) S += (rv[r] > tau) ? 1 : 0;
            #pragma unroll
            for (int o = 16; o; o >>= 1) S += __shfl_xor_sync(0xffffffffu, S, o);

            th = tau;
            float ssum = gfin;
            if (S > KSEL) {                          // rare: bisect K-th largest z
                useGe = 1;
                float lo = tau, hi = zmax;
                for (int it = 0; it < 48; ++it) {
                    float mid = 0.5f * (lo + hi);
                    int c = 0;
                    #pragma unroll
                    for (int r = 0; r < 8; ++r) c += (rv[r] >= mid) ? 1 : 0;
                    #pragma unroll
                    for (int o = 16; o; o >>= 1) c += __shfl_xor_sync(0xffffffffu, c, o);
                    if (c >= KSEL) lo = mid; else hi = mid;
                }
                th = lo;
                ssum = 0.f;
                #pragma unroll
                for (int r = 0; r < 8; ++r) {
                    float z = rv[r], d = z - tau;
                    if (z >= th && d > 0.f) ssum = fmaf(d, d, ssum);
                }
                #pragma unroll
                for (int o = 16; o; o >>= 1) ssum += __shfl_xor_sync(0xffffffffu, ssum, o);
            }
            inv = 1.0f / (ssum + 1e-8f);
            #pragma unroll
            for (int r = 0; r < 8; ++r) {            // exact num_selected
                float z = rv[r], d = z - tau;
                bool keep = useGe ? (z >= th && d > 0.f) : (d > 0.f);
                float w = keep ? d * d * inv : 0.f;
                sel += (w > 1e-6f);
            }
        } else {
            const float* cb = useSmem ? cand : (logits + (size_t)row * NCOLS);
            const float  sc = useSmem ? 1.0f : 0.5f;
            const int    n  = useSmem ? cn : NCOLS;

            float gfin = 0.f;
            for (int it = 0; it < 24; ++it) {
                float g = 0.f, gp = 0.f;
                for (int i = lane; i < n; i += 32) {
                    float d = sc * cb[i] - tau;
                    if (d > 0.f) { g = fmaf(d, d, g); gp += d; }
                }
                #pragma unroll
                for (int o = 16; o; o >>= 1) {
                    g  += __shfl_xor_sync(0xffffffffu, g,  o);
                    gp += __shfl_xor_sync(0xffffffffu, gp, o);
                }
                gfin = g;
                g -= 1.0f;
                if (gp <= 0.f) break;
                float step = g / (2.0f * gp);
                tau += step;
                if (step < 1e-7f) break;
            }
            int S = 0;
            for (int i = lane; i < n; i += 32) S += (sc * cb[i] > tau) ? 1 : 0;
            #pragma unroll
            for (int o = 16; o; o >>= 1) S += __shfl_xor_sync(0xffffffffu, S, o);

            th = tau;
            float ssum = gfin;
            if (S > KSEL) {
                useGe = 1;
                float lo = tau, hi = zmax;
                for (int it = 0; it < 48; ++it) {
                    float mid = 0.5f * (lo + hi);
                    int c = 0;
                    for (int i = lane; i < n; i += 32) c += (sc * cb[i] >= mid) ? 1 : 0;
                    #pragma unroll
                    for (int o = 16; o; o >>= 1) c += __shfl_xor_sync(0xffffffffu, c, o);
                    if (c >= KSEL) lo = mid; else hi = mid;
                }
                th = lo;
                ssum = 0.f;
                for (int i = lane; i < n; i += 32) {
                    float z = sc * cb[i], d = z - tau;
                    if (z >= th && d > 0.f) ssum = fmaf(d, d, ssum);
                }
                #pragma unroll
                for (int o = 16; o; o >>= 1) ssum += __shfl_xor_sync(0xffffffffu, ssum, o);
            }
            inv = 1.0f / (ssum + 1e-8f);
            for (int i = lane; i < n; i += 32) {
                float z = sc * cb[i], d = z - tau;
                bool keep = useGe ? (z >= th && d > 0.f) : (d > 0.f);
                float w = keep ? d * d * inv : 0.f;
                sel += (w > 1e-6f);
            }
        }
        #pragma unroll
        for (int o = 16; o; o >>= 1) sel += __shfl_xor_sync(0xffffffffu, sel, o);
        if (lane == 0) {
            s_tau = tau; s_th = th; s_useGe = useGe; s_inv = inv;
            out_cnt[row] = (float)sel;
        }
    }
    __syncthreads();                                 // barrier 4 (last)

    const float tau = s_tau, th = s_th, inv = s_inv;
    const bool  useGe = (s_useGe != 0);

    // ---------- Output: barrier-free stream (L2 re-read -> weights -> __stcs) ----------
    #pragma unroll 4
    for (int j = 0; j < V4; ++j) {
        float4 t = src[tid + j * NT];                // L2 hit
        float4 w;
        {
            float z = 0.5f * t.x, d = z - tau;
            bool keep = useGe ? (z >= th && d > 0.f) : (d > 0.f);
            w.x = keep ? d * d * inv : 0.f;
        }
        {
            float z = 0.5f * t.y, d = z - tau;
            bool keep = useGe ? (z >= th && d > 0.f) : (d > 0.f);
            w.y = keep ? d * d * inv : 0.f;
        }
        {
            float z = 0.5f * t.z, d = z - tau;
            bool keep = useGe ? (z >= th && d > 0.f) : (d > 0.f);
            w.z = keep ? d * d * inv : 0.f;
        }
        {
            float z = 0.5f * t.w, d = z - tau;
            bool keep = useGe ? (z >= th && d > 0.f) : (d > 0.f);
            w.w = keep ? d * d * inv : 0.f;
        }
        __stcs(&dst[tid + j * NT], w);
    }
}

extern "C" void kernel_launch(void* const* d_in, const int* in_sizes, int n_in,
                              void* d_out, int out_size)
{
    const float* logits = (const float*)d_in[0];
    float* out = (float*)d_out;
    const int B = in_sizes[0] / NCOLS;
    entmax_topk_kernel<<<B, NT>>>(logits, out, out + (size_t)B * NCOLS);
}